// round 13
// baseline (speedup 1.0000x reference)
#include <cuda_runtime.h>
#include <cuda_fp16.h>
#include <cstdint>

#define Bsz 2
#define Ssz 2048
#define Dsz 1024
#define Hsz 16
#define HDsz 64
#define Msz (Bsz*Ssz)   // 4096

#define QSCALE 0.18033688011112042f   // 0.125 * log2(e)

// fp16 scratch (allocation-free)
__device__ __align__(16) __half g_xh[Msz*Dsz];
__device__ __align__(16) __half g_wh[4*Dsz*Dsz];       // Wq(pre-scaled),Wk,Wv,Wo
__device__ __align__(16) __half g_q[Bsz*Hsz*Ssz*HDsz]; // [B,H,S,HD]
__device__ __align__(16) __half g_k[Bsz*Hsz*Ssz*HDsz]; // [B,H,S,HD]
__device__ __align__(16) __half g_v[Bsz*Hsz*Ssz*HDsz]; // [B,H,HD,S] (transposed)
__device__ __align__(16) __half g_zh[Msz*Dsz];

// [0]=projfused ctr, [1]=attn ctr, [2..34)=x m-tile ctrs (target 2),
// [34..66)=w strip ctrs (target 2)
__device__ unsigned int g_sync[66];

// ---------------- helpers ----------------

__device__ __forceinline__ void cp16(uint32_t smem_addr, const void* gptr) {
    asm volatile("cp.async.cg.shared.global [%0], [%1], 16;"
                 :: "r"(smem_addr), "l"(gptr));
}

__device__ __forceinline__ void mma16(float* d, const uint32_t* a, uint32_t b0, uint32_t b1) {
    asm volatile(
        "mma.sync.aligned.m16n8k16.row.col.f32.f16.f16.f32 "
        "{%0,%1,%2,%3}, {%4,%5,%6,%7}, {%8,%9}, {%0,%1,%2,%3};"
        : "+f"(d[0]), "+f"(d[1]), "+f"(d[2]), "+f"(d[3])
        : "r"(a[0]), "r"(a[1]), "r"(a[2]), "r"(a[3]), "r"(b0), "r"(b1));
}

__device__ __forceinline__ void ldsm4(uint32_t* r, uint32_t addr) {
    asm volatile("ldmatrix.sync.aligned.m8n8.x4.shared.b16 {%0,%1,%2,%3}, [%4];"
                 : "=r"(r[0]), "=r"(r[1]), "=r"(r[2]), "=r"(r[3]) : "r"(addr));
}

__device__ __forceinline__ uint32_t packh2(float lo, float hi) {
    half2 h = __floats2half2_rn(lo, hi);
    return *(uint32_t*)&h;
}

__device__ __forceinline__ float ex2f(float x) {
    float y;
    asm("ex2.approx.ftz.f32 %0, %1;" : "=f"(y) : "f"(x));
    return y;
}

__device__ __forceinline__ uint32_t h2ex2(uint32_t x) {
    uint32_t y;
    asm("ex2.approx.f16x2 %0, %1;" : "=r"(y) : "r"(x));
    return y;
}

__device__ __forceinline__ void publish(unsigned int* ctr, int tid) {
    __threadfence();
    __syncthreads();
    if (tid == 0) atomicAdd(ctr, 1u);
}

__device__ __forceinline__ void wait_ge(const unsigned int* ctr, unsigned target, int tid) {
    if (tid == 0) {
        volatile const unsigned int* p = ctr;
        while (*p < target) __nanosleep(64);
    }
    __syncthreads();
}

// convert 64 rows x 1024 cols fp32 -> fp16 (scaled); 256 threads
__device__ __forceinline__ void convert_block(
    const float* __restrict__ src, __half* __restrict__ dst,
    size_t elem0, float sc, int tid)
{
    const float4* s4 = (const float4*)(src + elem0);
    half2* d2 = (half2*)(dst + elem0);
#pragma unroll 8
    for (int it = 0; it < 64; it++) {
        int i = it * 256 + tid;
        float4 v = s4[i];
        d2[2 * i]     = __floats2half2_rn(v.x * sc, v.y * sc);
        d2[2 * i + 1] = __floats2half2_rn(v.z * sc, v.w * sc);
    }
}

// ================= fp16 MMA GEMM tile (NT): BK=64, 2-stage, ONE sync/iter =================

#define SROW 36                    // words per 64-half row (32 + 4 pad)
#define GBUF (128 * SROW)
#define GEMM_SMEM_BYTES (4 * GBUF * 4)   // 73728

// MODE 0: half [B,H,S,HD]; 1: V transposed half [B,H,HD,S]; 2: fp32 [M,D]
template<int MODE>
__device__ __forceinline__ void gemm_tile(
    const __half* __restrict__ A, const __half* __restrict__ W,
    const float* __restrict__ bias, float bscale, void* __restrict__ outp,
    int m0, int n0)
{
    extern __shared__ uint32_t smw[];
    const int tid = threadIdx.x;
    const int lane = tid & 31, warp = tid >> 5;
    const int g = lane >> 2, cq = lane & 3;
    const int wm = warp >> 2, wn = warp & 3;

    const __half* Ap = A + (size_t)m0 * Dsz;
    const __half* Wp = W + (size_t)n0 * Dsz;
    const uint32_t sbase = (uint32_t)__cvta_generic_to_shared(smw);

    const uint32_t offA = (uint32_t)(((lane & 7) + 8 * ((lane >> 3) & 1)) * SROW * 4
                                     + (lane >> 4) * 16);
    const uint32_t offB = (uint32_t)(((lane & 7) + 8 * (lane >> 4)) * SROW * 4
                                     + ((lane >> 3) & 1) * 16);

    float acc[4][4][4];
#pragma unroll
    for (int mi = 0; mi < 4; mi++)
#pragma unroll
        for (int nj = 0; nj < 4; nj++)
#pragma unroll
            for (int t = 0; t < 4; t++) acc[mi][nj][t] = 0.f;

    auto issue = [&](int buf, int k0) {
#pragma unroll
        for (int p = 0; p < 4; p++) {
            int idx = tid + p * 256;
            int row = idx >> 3;
            int c   = idx & 7;
            uint32_t off = (uint32_t)((buf * GBUF + row * SROW + c * 4) * 4);
            cp16(sbase + off,                Ap + (size_t)row * Dsz + k0 + c * 8);
            cp16(sbase + off + 2 * GBUF * 4, Wp + (size_t)row * Dsz + k0 + c * 8);
        }
        asm volatile("cp.async.commit_group;");
    };

    issue(0, 0);

    const int T = Dsz / 64;
    for (int t = 0; t < T; t++) {
        asm volatile("cp.async.wait_group 0;");
        __syncthreads();
        if (t + 1 < T) issue((t + 1) & 1, (t + 1) * 64);

        const uint32_t aBuf = sbase + (uint32_t)((t & 1) * GBUF * 4);
        const uint32_t bBuf = sbase + (uint32_t)((2 + (t & 1)) * GBUF * 4);
#pragma unroll
        for (int kk = 0; kk < 4; kk++) {
            uint32_t af[4][4], bf[2][4];
#pragma unroll
            for (int mi = 0; mi < 4; mi++)
                ldsm4(af[mi], aBuf + (uint32_t)((wm * 64 + mi * 16) * SROW * 4 + kk * 32) + offA);
#pragma unroll
            for (int p = 0; p < 2; p++)
                ldsm4(bf[p], bBuf + (uint32_t)((wn * 32 + p * 16) * SROW * 4 + kk * 32) + offB);
#pragma unroll
            for (int mi = 0; mi < 4; mi++)
#pragma unroll
                for (int nj = 0; nj < 4; nj++)
                    mma16(acc[mi][nj], af[mi], bf[nj >> 1][(nj & 1) * 2], bf[nj >> 1][(nj & 1) * 2 + 1]);
        }
    }

#pragma unroll
    for (int mi = 0; mi < 4; mi++) {
        int m_lo = m0 + wm * 64 + mi * 16 + g;
        int m_hi = m_lo + 8;
#pragma unroll
        for (int nj = 0; nj < 4; nj++) {
            int n = n0 + wn * 32 + nj * 8 + 2 * cq;
            float b0 = bias[n] * bscale, b1 = bias[n + 1] * bscale;
            float v00 = acc[mi][nj][0] + b0, v01 = acc[mi][nj][1] + b1;
            float v10 = acc[mi][nj][2] + b0, v11 = acc[mi][nj][3] + b1;
            if (MODE == 0) {
                __half* out = (__half*)outp;
                int h = n >> 6, e = n & 63;
                int bb = m_lo >> 11, s = m_lo & 2047;
                *(half2*)(out + (((size_t)(bb * Hsz + h) * Ssz) + s) * HDsz + e) =
                    __floats2half2_rn(v00, v01);
                bb = m_hi >> 11; s = m_hi & 2047;
                *(half2*)(out + (((size_t)(bb * Hsz + h) * Ssz) + s) * HDsz + e) =
                    __floats2half2_rn(v10, v11);
            } else if (MODE == 1) {
                __half* out = (__half*)outp;
                int h = n >> 6, e = n & 63;
                int bb = m_lo >> 11, s = m_lo & 2047;
                size_t base = ((size_t)(bb * Hsz + h) * HDsz + e) * Ssz + s;
                out[base]       = __float2half_rn(v00);
                out[base + Ssz] = __float2half_rn(v01);
                bb = m_hi >> 11; s = m_hi & 2047;
                base = ((size_t)(bb * Hsz + h) * HDsz + e) * Ssz + s;
                out[base]       = __float2half_rn(v10);
                out[base + Ssz] = __float2half_rn(v11);
            } else {
                float* out = (float*)outp;
                *(float2*)(out + (size_t)m_lo * Dsz + n) = make_float2(v00, v01);
                *(float2*)(out + (size_t)m_hi * Dsz + n) = make_float2(v10, v11);
            }
        }
    }
}

// ================= fused preround + QKV projection =================
// Queue (896 units, producers strictly first):
//   [0,64):   X convert units: mt = u>>1, half = u&1 (64 rows). Publish x_ctr[mt].
//   [64,128): W convert units: v = u-64, ws = v>>1 (which = ws>>3, strip = ws&7),
//             half = v&1. Publish w_ctr[ws]. (Wo strips ws>=24: no consumer here;
//             outproj kernel launches later — kernel boundary orders it.)
//   [128,896): proj tiles (R10 order): t = u-128, which = t>>8, mt = (t&255)>>3,
//             nt = t&7. Waits x_ctr[mt]>=2 && w_ctr[which*8+nt]>=2.

#define N_PF_UNITS 896
#define PF_GRID 296

__global__ __launch_bounds__(256) void projfused_kernel(
    const float* __restrict__ X,  const float* __restrict__ Wq,
    const float* __restrict__ Wk, const float* __restrict__ Wv,
    const float* __restrict__ Wo,
    const float* __restrict__ bq, const float* __restrict__ bk,
    const float* __restrict__ bv)
{
    __shared__ unsigned int s_u;
    const int tid = threadIdx.x;

    for (;;) {
        if (tid == 0) s_u = atomicAdd(&g_sync[0], 1u);
        __syncthreads();
        const unsigned u = s_u;
        if (u >= N_PF_UNITS) break;

        if (u < 64) {
            const int mt = (int)(u >> 1);
            const int half = (int)(u & 1);
            convert_block(X, g_xh, ((size_t)mt * 128 + half * 64) * Dsz, 1.0f, tid);
            publish(&g_sync[2 + mt], tid);
        } else if (u < 128) {
            const int v = (int)(u - 64);
            const int ws = v >> 1;               // 0..31
            const int which = ws >> 3;           // 0..3
            const int strip = ws & 7;
            const int half = v & 1;
            const float* src = (which == 0) ? Wq : (which == 1) ? Wk
                             : (which == 2) ? Wv : Wo;
            const float sc = (which == 0) ? QSCALE : 1.0f;
            convert_block(src, g_wh + (size_t)which * Dsz * Dsz,
                          ((size_t)strip * 128 + half * 64) * Dsz, sc, tid);
            publish(&g_sync[34 + ws], tid);
        } else {
            const unsigned t = u - 128;
            const int which = (int)(t >> 8);
            const int rem = (int)(t & 255);
            const int mt = rem >> 3;
            const int nt = rem & 7;
            wait_ge(&g_sync[2 + mt], 2u, tid);
            wait_ge(&g_sync[34 + which * 8 + nt], 2u, tid);
            const int m0 = mt << 7, n0 = nt << 7;
            if (which == 0)
                gemm_tile<0>(g_xh, g_wh, bq, QSCALE, g_q, m0, n0);
            else if (which == 1)
                gemm_tile<0>(g_xh, g_wh + (size_t)Dsz * Dsz, bk, 1.0f, g_k, m0, n0);
            else
                gemm_tile<1>(g_xh, g_wh + 2 * (size_t)Dsz * Dsz, bv, 1.0f, g_v, m0, n0);
        }
    }
}

__global__ __launch_bounds__(256) void outproj_kernel(
    const float* __restrict__ bo, float* __restrict__ out)
{
    gemm_tile<2>(g_zh, g_wh + 3 * (size_t)Dsz * Dsz, bo, 1.0f, out,
                 blockIdx.y * 128, blockIdx.x * 128);
}

// ================= persistent fused causal flash attention (R10) =================

#define AQT 128
#define NSTG 4
#define QOFF 0
#define QWORDS (128 * SROW)          // 4608
#define KOFF QWORDS
#define KBUF (64 * SROW)             // 2304
#define VOFF (KOFF + NSTG * KBUF)
#define ATT_SMEM_WORDS (QWORDS + 2 * NSTG * KBUF)
#define ATT_SMEM_BYTES (ATT_SMEM_WORDS * 4)   // 92160
#define N_UNITS (Bsz * Hsz * (Ssz / AQT))     // 512
#define ATT_GRID 296

__global__ __launch_bounds__(256, 2) void attn_kernel()
{
    extern __shared__ uint32_t smw[];
    __shared__ unsigned int s_u;
    const uint32_t sbase = (uint32_t)__cvta_generic_to_shared(smw);

    const int tid = threadIdx.x;
    const int w = tid >> 5, lane = tid & 31;
    const int g = lane >> 2, cq = lane & 3;

    const uint32_t offB = (uint32_t)(((lane & 7) + 8 * (lane >> 4)) * SROW * 4
                                     + ((lane >> 3) & 1) * 16);

    for (;;) {
        if (tid == 0) s_u = atomicAdd(&g_sync[1], 1u);
        __syncthreads();
        const unsigned u = s_u;
        if (u >= N_UNITS) break;

        const int qt = 15 - (int)(u >> 5);   // heavy tiles first
        const int bhid = (int)(u & 31);
        const int b = bhid >> 4, h = bhid & 15;
        const int q0 = qt * AQT;

        const size_t bh = (size_t)(b * Hsz + h);
        const __half* Qp = g_q + (bh * Ssz + q0) * HDsz;
        const __half* Kp = g_k + bh * Ssz * HDsz;
        const __half* Vp = g_v + bh * HDsz * Ssz;

        auto issueKV = [&](int stg, int k0) {
#pragma unroll
            for (int p = 0; p < 2; p++) {
                int idx = tid + p * 256;
                int row = idx >> 3;
                int c   = idx & 7;
                uint32_t offK = (uint32_t)((KOFF + stg * KBUF + row * SROW + c * 4) * 4);
                cp16(sbase + offK, Kp + ((size_t)(k0 + row)) * HDsz + c * 8);
                uint32_t offV = (uint32_t)((VOFF + stg * KBUF + row * SROW + c * 4) * 4);
                cp16(sbase + offV, Vp + (size_t)row * Ssz + k0 + c * 8);
            }
            asm volatile("cp.async.commit_group;");
        };

        const int nkt = (q0 + AQT) / 64;

        {
#pragma unroll
            for (int p = 0; p < 4; p++) {
                int idx = tid + p * 256;
                int row = idx >> 3;
                int c   = idx & 7;
                uint32_t off = (uint32_t)((QOFF + row * SROW + c * 4) * 4);
                cp16(sbase + off, Qp + (size_t)row * HDsz + c * 8);
            }
            issueKV(0, 0);
        }
        if (nkt > 1) issueKV(1, 64);

        float o[8][4];
#pragma unroll
        for (int nf = 0; nf < 8; nf++)
#pragma unroll
            for (int t = 0; t < 4; t++) o[nf][t] = 0.f;
        float m_lo = -1e30f, m_hi = -1e30f, l_lo = 0.f, l_hi = 0.f;
        uint32_t p0r[8], p1r[8];
        uint32_t qa[4][4];

        const int q_lo = q0 + w * 16 + g;
        const int q_hi = q_lo + 8;
        const int warp_min_row = q0 + w * 16;

        auto pv_block = [&](int stg) {
            const uint32_t vBuf = sbase + (uint32_t)((VOFF + stg * KBUF) * 4);
#pragma unroll
            for (int kk = 0; kk < 4; kk++) {
                uint32_t pa[4] = { p0r[2 * kk], p1r[2 * kk], p0r[2 * kk + 1], p1r[2 * kk + 1] };
#pragma unroll
                for (int pf = 0; pf < 4; pf++) {
                    uint32_t bf[4];
                    ldsm4(bf, vBuf + (uint32_t)(pf * 16 * SROW * 4 + kk * 32) + offB);
                    mma16(o[2 * pf],     pa, bf[0], bf[1]);
                    mma16(o[2 * pf + 1], pa, bf[2], bf[3]);
                }
            }
        };

        for (int jt = 0; jt < nkt; jt++) {
            const int k0 = jt * 64;
            const int stg = jt & (NSTG - 1);
            if (jt + 1 < nkt) asm volatile("cp.async.wait_group 1;");
            else              asm volatile("cp.async.wait_group 0;");
            __syncthreads();
            if (jt + 2 < nkt) issueKV((jt + 2) & (NSTG - 1), (jt + 2) * 64);

            if (jt == 0) {
                const int r = w * 16 + g;
#pragma unroll
                for (int kk = 0; kk < 4; kk++) {
                    const uint32_t* p0 = smw + QOFF + r * SROW + kk * 8 + cq;
                    qa[kk][0] = p0[0];
                    qa[kk][1] = p0[8 * SROW];
                    qa[kk][2] = p0[4];
                    qa[kk][3] = p0[8 * SROW + 4];
                }
            }

            float s[8][4];
#pragma unroll
            for (int nf = 0; nf < 8; nf++)
#pragma unroll
                for (int t = 0; t < 4; t++) s[nf][t] = 0.f;

            const uint32_t kBuf = sbase + (uint32_t)((KOFF + stg * KBUF) * 4);
#pragma unroll
            for (int kk = 0; kk < 4; kk++) {
#pragma unroll
                for (int pf = 0; pf < 4; pf++) {
                    uint32_t bf[4];
                    ldsm4(bf, kBuf + (uint32_t)(pf * 16 * SROW * 4 + kk * 32) + offB);
                    mma16(s[2 * pf],     qa[kk], bf[0], bf[1]);
                    mma16(s[2 * pf + 1], qa[kk], bf[2], bf[3]);
                }
            }

            if (jt > 0) pv_block((jt - 1) & (NSTG - 1));

            const bool diag = (k0 + 63 > warp_min_row);
            if (diag) {
#pragma unroll
                for (int nf = 0; nf < 8; nf++) {
                    int n0c = k0 + nf * 8 + 2 * cq;
                    if (n0c     > q_lo) s[nf][0] = -1e30f;
                    if (n0c + 1 > q_lo) s[nf][1] = -1e30f;
                    if (n0c     > q_hi) s[nf][2] = -1e30f;
                    if (n0c + 1 > q_hi) s[nf][3] = -1e30f;
                }
            }

            float mx0 = -1e30f, mx1 = -1e30f;
#pragma unroll
            for (int nf = 0; nf < 8; nf++) {
                mx0 = fmaxf(mx0, fmaxf(s[nf][0], s[nf][1]));
                mx1 = fmaxf(mx1, fmaxf(s[nf][2], s[nf][3]));
            }
            mx0 = fmaxf(mx0, __shfl_xor_sync(0xffffffffu, mx0, 1));
            mx0 = fmaxf(mx0, __shfl_xor_sync(0xffffffffu, mx0, 2));
            mx1 = fmaxf(mx1, __shfl_xor_sync(0xffffffffu, mx1, 1));
            mx1 = fmaxf(mx1, __shfl_xor_sync(0xffffffffu, mx1, 2));

            float mn0 = fmaxf(m_lo, mx0), mn1 = fmaxf(m_hi, mx1);
            float corr0 = ex2f(m_lo - mn0), corr1 = ex2f(m_hi - mn1);
            m_lo = mn0; m_hi = mn1;

#pragma unroll
            for (int nf = 0; nf < 8; nf++) {
                o[nf][0] *= corr0; o[nf][1] *= corr0;
                o[nf][2] *= corr1; o[nf][3] *= corr1;
            }

            float sl = 0.f, sh = 0.f;
#pragma unroll
            for (int nf = 0; nf < 8; nf++) {
                p0r[nf] = h2ex2(packh2(s[nf][0] - mn0, s[nf][1] - mn0));
                p1r[nf] = h2ex2(packh2(s[nf][2] - mn1, s[nf][3] - mn1));
                float2 a = __half22float2(*(half2*)&p0r[nf]);
                float2 c = __half22float2(*(half2*)&p1r[nf]);
                sl += a.x + a.y;
                sh += c.x + c.y;
            }
            sl += __shfl_xor_sync(0xffffffffu, sl, 1);
            sl += __shfl_xor_sync(0xffffffffu, sl, 2);
            sh += __shfl_xor_sync(0xffffffffu, sh, 1);
            sh += __shfl_xor_sync(0xffffffffu, sh, 2);
            l_lo = l_lo * corr0 + sl;
            l_hi = l_hi * corr1 + sh;
        }

        pv_block((nkt - 1) & (NSTG - 1));

        const float inv0 = 1.f / l_lo, inv1 = 1.f / l_hi;
        __half* zlo = g_zh + ((size_t)b * Ssz + q_lo) * Dsz + h * HDsz;
        __half* zhi = g_zh + ((size_t)b * Ssz + q_hi) * Dsz + h * HDsz;
#pragma unroll
        for (int nf = 0; nf < 8; nf++) {
            int cc = nf * 8 + 2 * cq;
            *(half2*)(zlo + cc) = __floats2half2_rn(o[nf][0] * inv0, o[nf][1] * inv0);
            *(half2*)(zhi + cc) = __floats2half2_rn(o[nf][2] * inv1, o[nf][3] * inv1);
        }
    }
}

// ================= launch =================

extern "C" void kernel_launch(void* const* d_in, const int* in_sizes, int n_in,
                              void* d_out, int out_size)
{
    (void)in_sizes; (void)n_in; (void)out_size;
    const float* X  = (const float*)d_in[0];
    const float* Wq = (const float*)d_in[1];
    const float* bq = (const float*)d_in[2];
    const float* Wk = (const float*)d_in[3];
    const float* bk = (const float*)d_in[4];
    const float* Wv = (const float*)d_in[5];
    const float* bv = (const float*)d_in[6];
    const float* Wo = (const float*)d_in[7];
    const float* bo = (const float*)d_in[8];
    float* out = (float*)d_out;

    cudaFuncSetAttribute(projfused_kernel,
                         cudaFuncAttributeMaxDynamicSharedMemorySize, GEMM_SMEM_BYTES);
    cudaFuncSetAttribute(outproj_kernel,
                         cudaFuncAttributeMaxDynamicSharedMemorySize, GEMM_SMEM_BYTES);
    cudaFuncSetAttribute(attn_kernel,
                         cudaFuncAttributeMaxDynamicSharedMemorySize, ATT_SMEM_BYTES);

    void* sync_addr = nullptr;
    cudaGetSymbolAddress(&sync_addr, g_sync);
    cudaMemsetAsync(sync_addr, 0, 66 * sizeof(unsigned int));

    projfused_kernel<<<PF_GRID, 256, GEMM_SMEM_BYTES>>>(X, Wq, Wk, Wv, Wo, bq, bk, bv);

    attn_kernel<<<ATT_GRID, 256, ATT_SMEM_BYTES>>>();

    outproj_kernel<<<dim3(Dsz / 128, Msz / 128, 1), 256, GEMM_SMEM_BYTES>>>(bo, out);
}

// round 14
// speedup vs baseline: 1.0281x; 1.0281x over previous
#include <cuda_runtime.h>
#include <cuda_fp16.h>
#include <cstdint>

#define Bsz 2
#define Ssz 2048
#define Dsz 1024
#define Hsz 16
#define HDsz 64
#define Msz (Bsz*Ssz)   // 4096

#define QSCALE 0.18033688011112042f   // 0.125 * log2(e)

// fp16 scratch (allocation-free)
__device__ __align__(16) __half g_xh[Msz*Dsz];
__device__ __align__(16) __half g_wh[4*Dsz*Dsz];       // Wq(pre-scaled),Wk,Wv,Wo
__device__ __align__(16) __half g_q[Bsz*Hsz*Ssz*HDsz]; // [B,H,S,HD]
__device__ __align__(16) __half g_k[Bsz*Hsz*Ssz*HDsz]; // [B,H,S,HD]
__device__ __align__(16) __half g_v[Bsz*Hsz*Ssz*HDsz]; // [B,H,HD,S] (transposed)
__device__ __align__(16) __half g_zh[Msz*Dsz];
__device__ unsigned int g_ctr[2];   // [0]=attn, [1]=proj work-steal counters

// ---------------- helpers ----------------

__device__ __forceinline__ void cp16(uint32_t smem_addr, const void* gptr) {
    asm volatile("cp.async.cg.shared.global [%0], [%1], 16;"
                 :: "r"(smem_addr), "l"(gptr));
}

__device__ __forceinline__ void mma16(float* d, const uint32_t* a, uint32_t b0, uint32_t b1) {
    asm volatile(
        "mma.sync.aligned.m16n8k16.row.col.f32.f16.f16.f32 "
        "{%0,%1,%2,%3}, {%4,%5,%6,%7}, {%8,%9}, {%0,%1,%2,%3};"
        : "+f"(d[0]), "+f"(d[1]), "+f"(d[2]), "+f"(d[3])
        : "r"(a[0]), "r"(a[1]), "r"(a[2]), "r"(a[3]), "r"(b0), "r"(b1));
}

__device__ __forceinline__ void ldsm4(uint32_t* r, uint32_t addr) {
    asm volatile("ldmatrix.sync.aligned.m8n8.x4.shared.b16 {%0,%1,%2,%3}, [%4];"
                 : "=r"(r[0]), "=r"(r[1]), "=r"(r[2]), "=r"(r[3]) : "r"(addr));
}

__device__ __forceinline__ uint32_t packh2(float lo, float hi) {
    half2 h = __floats2half2_rn(lo, hi);
    return *(uint32_t*)&h;
}

__device__ __forceinline__ float ex2f(float x) {
    float y;
    asm("ex2.approx.ftz.f32 %0, %1;" : "=f"(y) : "f"(x));
    return y;
}

__device__ __forceinline__ uint32_t h2ex2(uint32_t x) {
    uint32_t y;
    asm("ex2.approx.f16x2 %0, %1;" : "=r"(y) : "r"(x));
    return y;
}

// ---------------- pre-round: fp32 -> fp16 (Wq scaled by QSCALE) ----------------

__global__ __launch_bounds__(256) void preround_kernel(
    const float* __restrict__ X, const float* __restrict__ Wq,
    const float* __restrict__ Wk, const float* __restrict__ Wv,
    const float* __restrict__ Wo)
{
    const int z = blockIdx.z;
    const float* src;
    __half* dst;
    int iters;
    float sc = 1.0f;
    if (z == 0) { src = X; dst = g_xh; iters = 4; }
    else {
        src = (z == 1) ? Wq : (z == 2) ? Wk : (z == 3) ? Wv : Wo;
        dst = g_wh + (size_t)(z - 1) * Dsz * Dsz;
        iters = 1;
        if (z == 1) sc = QSCALE;
    }
#pragma unroll
    for (int it = 0; it < 4; it++) {
        if (it >= iters) break;
        size_t i = (size_t)(blockIdx.x * 256 + threadIdx.x) + (size_t)it * (1024 * 256);
        float4 v = ((const float4*)src)[i];
        half2* d2 = (half2*)dst;
        d2[2 * i]     = __floats2half2_rn(v.x * sc, v.y * sc);
        d2[2 * i + 1] = __floats2half2_rn(v.z * sc, v.w * sc);
    }
}

// ================= fp16 MMA GEMM tile (NT): BK=64, 3-stage ring, wait_group 1 =================

#define SROW 36                    // words per 64-half row (32 + 4 pad)
#define GBUF (128 * SROW)          // 4608 words per stage per matrix
#define GSTG 3
#define GEMM_SMEM_BYTES (2 * GSTG * GBUF * 4)   // 110592

// MODE 0: half [B,H,S,HD]; 1: V transposed half [B,H,HD,S]; 2: fp32 [M,D]
template<int MODE>
__device__ __forceinline__ void gemm_tile(
    const __half* __restrict__ A, const __half* __restrict__ W,
    const float* __restrict__ bias, float bscale, void* __restrict__ outp,
    int m0, int n0)
{
    extern __shared__ uint32_t smw[];
    const int tid = threadIdx.x;
    const int lane = tid & 31, warp = tid >> 5;
    const int g = lane >> 2, cq = lane & 3;
    const int wm = warp >> 2, wn = warp & 3;

    const __half* Ap = A + (size_t)m0 * Dsz;
    const __half* Wp = W + (size_t)n0 * Dsz;
    const uint32_t sbase = (uint32_t)__cvta_generic_to_shared(smw);

    const uint32_t offA = (uint32_t)(((lane & 7) + 8 * ((lane >> 3) & 1)) * SROW * 4
                                     + (lane >> 4) * 16);
    const uint32_t offB = (uint32_t)(((lane & 7) + 8 * (lane >> 4)) * SROW * 4
                                     + ((lane >> 3) & 1) * 16);

    float acc[4][4][4];
#pragma unroll
    for (int mi = 0; mi < 4; mi++)
#pragma unroll
        for (int nj = 0; nj < 4; nj++)
#pragma unroll
            for (int t = 0; t < 4; t++) acc[mi][nj][t] = 0.f;

    auto issue = [&](int stg, int k0) {
#pragma unroll
        for (int p = 0; p < 4; p++) {
            int idx = tid + p * 256;
            int row = idx >> 3;
            int c   = idx & 7;
            uint32_t off = (uint32_t)((stg * GBUF + row * SROW + c * 4) * 4);
            cp16(sbase + off,                   Ap + (size_t)row * Dsz + k0 + c * 8);
            cp16(sbase + off + GSTG * GBUF * 4, Wp + (size_t)row * Dsz + k0 + c * 8);
        }
        asm volatile("cp.async.commit_group;");
    };

    issue(0, 0);
    issue(1, 64);

    const int T = Dsz / 64;   // 16
    for (int t = 0; t < T; t++) {
        // stage t must be landed; stage t+1 may stay in flight
        if (t + 1 < T) asm volatile("cp.async.wait_group 1;");
        else           asm volatile("cp.async.wait_group 0;");
        __syncthreads();
        // stage (t+2)%3 was last read in iter t-1 (before the sync above)
        if (t + 2 < T) issue((t + 2) % GSTG, (t + 2) * 64);

        const int stg = t % GSTG;
        const uint32_t aBuf = sbase + (uint32_t)(stg * GBUF * 4);
        const uint32_t bBuf = sbase + (uint32_t)((GSTG + stg) * GBUF * 4);
#pragma unroll
        for (int kk = 0; kk < 4; kk++) {
            uint32_t af[4][4], bf[2][4];
#pragma unroll
            for (int mi = 0; mi < 4; mi++)
                ldsm4(af[mi], aBuf + (uint32_t)((wm * 64 + mi * 16) * SROW * 4 + kk * 32) + offA);
#pragma unroll
            for (int p = 0; p < 2; p++)
                ldsm4(bf[p], bBuf + (uint32_t)((wn * 32 + p * 16) * SROW * 4 + kk * 32) + offB);
#pragma unroll
            for (int mi = 0; mi < 4; mi++)
#pragma unroll
                for (int nj = 0; nj < 4; nj++)
                    mma16(acc[mi][nj], af[mi], bf[nj >> 1][(nj & 1) * 2], bf[nj >> 1][(nj & 1) * 2 + 1]);
        }
    }

#pragma unroll
    for (int mi = 0; mi < 4; mi++) {
        int m_lo = m0 + wm * 64 + mi * 16 + g;
        int m_hi = m_lo + 8;
#pragma unroll
        for (int nj = 0; nj < 4; nj++) {
            int n = n0 + wn * 32 + nj * 8 + 2 * cq;
            float b0 = bias[n] * bscale, b1 = bias[n + 1] * bscale;
            float v00 = acc[mi][nj][0] + b0, v01 = acc[mi][nj][1] + b1;
            float v10 = acc[mi][nj][2] + b0, v11 = acc[mi][nj][3] + b1;
            if (MODE == 0) {
                __half* out = (__half*)outp;
                int h = n >> 6, e = n & 63;
                int bb = m_lo >> 11, s = m_lo & 2047;
                *(half2*)(out + (((size_t)(bb * Hsz + h) * Ssz) + s) * HDsz + e) =
                    __floats2half2_rn(v00, v01);
                bb = m_hi >> 11; s = m_hi & 2047;
                *(half2*)(out + (((size_t)(bb * Hsz + h) * Ssz) + s) * HDsz + e) =
                    __floats2half2_rn(v10, v11);
            } else if (MODE == 1) {
                __half* out = (__half*)outp;
                int h = n >> 6, e = n & 63;
                int bb = m_lo >> 11, s = m_lo & 2047;
                size_t base = ((size_t)(bb * Hsz + h) * HDsz + e) * Ssz + s;
                out[base]       = __float2half_rn(v00);
                out[base + Ssz] = __float2half_rn(v01);
                bb = m_hi >> 11; s = m_hi & 2047;
                base = ((size_t)(bb * Hsz + h) * HDsz + e) * Ssz + s;
                out[base]       = __float2half_rn(v10);
                out[base + Ssz] = __float2half_rn(v11);
            } else {
                float* out = (float*)outp;
                *(float2*)(out + (size_t)m_lo * Dsz + n) = make_float2(v00, v01);
                *(float2*)(out + (size_t)m_hi * Dsz + n) = make_float2(v10, v11);
            }
        }
    }
}

// persistent QKV projection: 768 tiles work-stolen (R10-proven)
#define N_PROJ_TILES 768
#define PROJ_GRID 296

__global__ __launch_bounds__(256) void proj_kernel(
    const float* __restrict__ bq, const float* __restrict__ bk,
    const float* __restrict__ bv)
{
    __shared__ unsigned int s_u;
    const int tid = threadIdx.x;
    for (;;) {
        if (tid == 0) s_u = atomicAdd(&g_ctr[1], 1u);
        __syncthreads();
        const unsigned u = s_u;
        if (u >= N_PROJ_TILES) break;
        const int which = (int)(u >> 8);
        const int rem = (int)(u & 255);
        const int m0 = (rem >> 3) * 128;
        const int n0 = (rem & 7) * 128;
        if (which == 0)
            gemm_tile<0>(g_xh, g_wh, bq, QSCALE, g_q, m0, n0);
        else if (which == 1)
            gemm_tile<0>(g_xh, g_wh + (size_t)Dsz * Dsz, bk, 1.0f, g_k, m0, n0);
        else
            gemm_tile<1>(g_xh, g_wh + 2 * (size_t)Dsz * Dsz, bv, 1.0f, g_v, m0, n0);
    }
}

__global__ __launch_bounds__(256) void outproj_kernel(
    const float* __restrict__ bo, float* __restrict__ out)
{
    gemm_tile<2>(g_zh, g_wh + 3 * (size_t)Dsz * Dsz, bo, 1.0f, out,
                 blockIdx.y * 128, blockIdx.x * 128);
}

// ================= persistent fused causal flash attention (R10) =================

#define AQT 128
#define NSTG 4
#define QOFF 0
#define QWORDS (128 * SROW)          // 4608
#define KOFF QWORDS
#define KBUF (64 * SROW)             // 2304
#define VOFF (KOFF + NSTG * KBUF)
#define ATT_SMEM_WORDS (QWORDS + 2 * NSTG * KBUF)
#define ATT_SMEM_BYTES (ATT_SMEM_WORDS * 4)   // 92160
#define N_UNITS (Bsz * Hsz * (Ssz / AQT))     // 512
#define ATT_GRID 296

__global__ __launch_bounds__(256, 2) void attn_kernel()
{
    extern __shared__ uint32_t smw[];
    __shared__ unsigned int s_u;
    const uint32_t sbase = (uint32_t)__cvta_generic_to_shared(smw);

    const int tid = threadIdx.x;
    const int w = tid >> 5, lane = tid & 31;
    const int g = lane >> 2, cq = lane & 3;

    const uint32_t offB = (uint32_t)(((lane & 7) + 8 * (lane >> 4)) * SROW * 4
                                     + ((lane >> 3) & 1) * 16);

    for (;;) {
        if (tid == 0) s_u = atomicAdd(&g_ctr[0], 1u);
        __syncthreads();
        const unsigned u = s_u;
        if (u >= N_UNITS) break;

        const int qt = 15 - (int)(u >> 5);   // heavy tiles first
        const int bhid = (int)(u & 31);
        const int b = bhid >> 4, h = bhid & 15;
        const int q0 = qt * AQT;

        const size_t bh = (size_t)(b * Hsz + h);
        const __half* Qp = g_q + (bh * Ssz + q0) * HDsz;
        const __half* Kp = g_k + bh * Ssz * HDsz;
        const __half* Vp = g_v + bh * HDsz * Ssz;

        auto issueKV = [&](int stg, int k0) {
#pragma unroll
            for (int p = 0; p < 2; p++) {
                int idx = tid + p * 256;
                int row = idx >> 3;
                int c   = idx & 7;
                uint32_t offK = (uint32_t)((KOFF + stg * KBUF + row * SROW + c * 4) * 4);
                cp16(sbase + offK, Kp + ((size_t)(k0 + row)) * HDsz + c * 8);
                uint32_t offV = (uint32_t)((VOFF + stg * KBUF + row * SROW + c * 4) * 4);
                cp16(sbase + offV, Vp + (size_t)row * Ssz + k0 + c * 8);
            }
            asm volatile("cp.async.commit_group;");
        };

        const int nkt = (q0 + AQT) / 64;

        {
#pragma unroll
            for (int p = 0; p < 4; p++) {
                int idx = tid + p * 256;
                int row = idx >> 3;
                int c   = idx & 7;
                uint32_t off = (uint32_t)((QOFF + row * SROW + c * 4) * 4);
                cp16(sbase + off, Qp + (size_t)row * HDsz + c * 8);
            }
            issueKV(0, 0);
        }
        if (nkt > 1) issueKV(1, 64);

        float o[8][4];
#pragma unroll
        for (int nf = 0; nf < 8; nf++)
#pragma unroll
            for (int t = 0; t < 4; t++) o[nf][t] = 0.f;
        float m_lo = -1e30f, m_hi = -1e30f, l_lo = 0.f, l_hi = 0.f;
        uint32_t p0r[8], p1r[8];
        uint32_t qa[4][4];

        const int q_lo = q0 + w * 16 + g;
        const int q_hi = q_lo + 8;
        const int warp_min_row = q0 + w * 16;

        auto pv_block = [&](int stg) {
            const uint32_t vBuf = sbase + (uint32_t)((VOFF + stg * KBUF) * 4);
#pragma unroll
            for (int kk = 0; kk < 4; kk++) {
                uint32_t pa[4] = { p0r[2 * kk], p1r[2 * kk], p0r[2 * kk + 1], p1r[2 * kk + 1] };
#pragma unroll
                for (int pf = 0; pf < 4; pf++) {
                    uint32_t bf[4];
                    ldsm4(bf, vBuf + (uint32_t)(pf * 16 * SROW * 4 + kk * 32) + offB);
                    mma16(o[2 * pf],     pa, bf[0], bf[1]);
                    mma16(o[2 * pf + 1], pa, bf[2], bf[3]);
                }
            }
        };

        for (int jt = 0; jt < nkt; jt++) {
            const int k0 = jt * 64;
            const int stg = jt & (NSTG - 1);
            if (jt + 1 < nkt) asm volatile("cp.async.wait_group 1;");
            else              asm volatile("cp.async.wait_group 0;");
            __syncthreads();
            if (jt + 2 < nkt) issueKV((jt + 2) & (NSTG - 1), (jt + 2) * 64);

            if (jt == 0) {
                const int r = w * 16 + g;
#pragma unroll
                for (int kk = 0; kk < 4; kk++) {
                    const uint32_t* p0 = smw + QOFF + r * SROW + kk * 8 + cq;
                    qa[kk][0] = p0[0];
                    qa[kk][1] = p0[8 * SROW];
                    qa[kk][2] = p0[4];
                    qa[kk][3] = p0[8 * SROW + 4];
                }
            }

            float s[8][4];
#pragma unroll
            for (int nf = 0; nf < 8; nf++)
#pragma unroll
                for (int t = 0; t < 4; t++) s[nf][t] = 0.f;

            const uint32_t kBuf = sbase + (uint32_t)((KOFF + stg * KBUF) * 4);
#pragma unroll
            for (int kk = 0; kk < 4; kk++) {
#pragma unroll
                for (int pf = 0; pf < 4; pf++) {
                    uint32_t bf[4];
                    ldsm4(bf, kBuf + (uint32_t)(pf * 16 * SROW * 4 + kk * 32) + offB);
                    mma16(s[2 * pf],     qa[kk], bf[0], bf[1]);
                    mma16(s[2 * pf + 1], qa[kk], bf[2], bf[3]);
                }
            }

            if (jt > 0) pv_block((jt - 1) & (NSTG - 1));

            const bool diag = (k0 + 63 > warp_min_row);
            if (diag) {
#pragma unroll
                for (int nf = 0; nf < 8; nf++) {
                    int n0c = k0 + nf * 8 + 2 * cq;
                    if (n0c     > q_lo) s[nf][0] = -1e30f;
                    if (n0c + 1 > q_lo) s[nf][1] = -1e30f;
                    if (n0c     > q_hi) s[nf][2] = -1e30f;
                    if (n0c + 1 > q_hi) s[nf][3] = -1e30f;
                }
            }

            float mx0 = -1e30f, mx1 = -1e30f;
#pragma unroll
            for (int nf = 0; nf < 8; nf++) {
                mx0 = fmaxf(mx0, fmaxf(s[nf][0], s[nf][1]));
                mx1 = fmaxf(mx1, fmaxf(s[nf][2], s[nf][3]));
            }
            mx0 = fmaxf(mx0, __shfl_xor_sync(0xffffffffu, mx0, 1));
            mx0 = fmaxf(mx0, __shfl_xor_sync(0xffffffffu, mx0, 2));
            mx1 = fmaxf(mx1, __shfl_xor_sync(0xffffffffu, mx1, 1));
            mx1 = fmaxf(mx1, __shfl_xor_sync(0xffffffffu, mx1, 2));

            float mn0 = fmaxf(m_lo, mx0), mn1 = fmaxf(m_hi, mx1);
            float corr0 = ex2f(m_lo - mn0), corr1 = ex2f(m_hi - mn1);
            m_lo = mn0; m_hi = mn1;

#pragma unroll
            for (int nf = 0; nf < 8; nf++) {
                o[nf][0] *= corr0; o[nf][1] *= corr0;
                o[nf][2] *= corr1; o[nf][3] *= corr1;
            }

            float sl = 0.f, sh = 0.f;
#pragma unroll
            for (int nf = 0; nf < 8; nf++) {
                p0r[nf] = h2ex2(packh2(s[nf][0] - mn0, s[nf][1] - mn0));
                p1r[nf] = h2ex2(packh2(s[nf][2] - mn1, s[nf][3] - mn1));
                float2 a = __half22float2(*(half2*)&p0r[nf]);
                float2 c = __half22float2(*(half2*)&p1r[nf]);
                sl += a.x + a.y;
                sh += c.x + c.y;
            }
            sl += __shfl_xor_sync(0xffffffffu, sl, 1);
            sl += __shfl_xor_sync(0xffffffffu, sl, 2);
            sh += __shfl_xor_sync(0xffffffffu, sh, 1);
            sh += __shfl_xor_sync(0xffffffffu, sh, 2);
            l_lo = l_lo * corr0 + sl;
            l_hi = l_hi * corr1 + sh;
        }

        pv_block((nkt - 1) & (NSTG - 1));

        const float inv0 = 1.f / l_lo, inv1 = 1.f / l_hi;
        __half* zlo = g_zh + ((size_t)b * Ssz + q_lo) * Dsz + h * HDsz;
        __half* zhi = g_zh + ((size_t)b * Ssz + q_hi) * Dsz + h * HDsz;
#pragma unroll
        for (int nf = 0; nf < 8; nf++) {
            int cc = nf * 8 + 2 * cq;
            *(half2*)(zlo + cc) = __floats2half2_rn(o[nf][0] * inv0, o[nf][1] * inv0);
            *(half2*)(zhi + cc) = __floats2half2_rn(o[nf][2] * inv1, o[nf][3] * inv1);
        }
    }
}

// ================= launch =================

extern "C" void kernel_launch(void* const* d_in, const int* in_sizes, int n_in,
                              void* d_out, int out_size)
{
    (void)in_sizes; (void)n_in; (void)out_size;
    const float* X  = (const float*)d_in[0];
    const float* Wq = (const float*)d_in[1];
    const float* bq = (const float*)d_in[2];
    const float* Wk = (const float*)d_in[3];
    const float* bk = (const float*)d_in[4];
    const float* Wv = (const float*)d_in[5];
    const float* bv = (const float*)d_in[6];
    const float* Wo = (const float*)d_in[7];
    const float* bo = (const float*)d_in[8];
    float* out = (float*)d_out;

    cudaFuncSetAttribute(proj_kernel,
                         cudaFuncAttributeMaxDynamicSharedMemorySize, GEMM_SMEM_BYTES);
    cudaFuncSetAttribute(outproj_kernel,
                         cudaFuncAttributeMaxDynamicSharedMemorySize, GEMM_SMEM_BYTES);
    cudaFuncSetAttribute(attn_kernel,
                         cudaFuncAttributeMaxDynamicSharedMemorySize, ATT_SMEM_BYTES);

    void* ctr_addr = nullptr;
    cudaGetSymbolAddress(&ctr_addr, g_ctr);
    cudaMemsetAsync(ctr_addr, 0, 2 * sizeof(unsigned int));

    preround_kernel<<<dim3(1024, 1, 5), 256>>>(X, Wq, Wk, Wv, Wo);

    proj_kernel<<<PROJ_GRID, 256, GEMM_SMEM_BYTES>>>(bq, bk, bv);

    attn_kernel<<<ATT_GRID, 256, ATT_SMEM_BYTES>>>();

    outproj_kernel<<<dim3(Dsz / 128, Msz / 128, 1), 256, GEMM_SMEM_BYTES>>>(bo, out);
}